// round 2
// baseline (speedup 1.0000x reference)
#include <cuda_runtime.h>
#include <cstdint>

// Problem: Quantizer — vector-quantization assignment.
//   x        [B,H,L,D] f32,  B=4,H=16,L=4096,D=64
//   c_sum    [H,S,D]   f32,  S=512
//   c_count  [H,S]     f32
// Outputs (concatenated in reference return order):
//   delta_onehot [B,H,L,S] f32   (134217728 elems)
//   c            [H,S,D]   f32   (524288 elems)
//
// argmin_s (|x|^2 - 2 x.c_s + |c_s|^2)  ==  argmin_s (|c_s|^2 - 2 x.c_s)
// (per-row constant |x|^2 dropped; monotone, argmin-preserving).

#define Bq 4
#define Hq 16
#define Lq 4096
#define Dq 64
#define Sq 512

#define ONEHOT_ELEMS ((size_t)Bq * Hq * Lq * Sq)

// Scratch (no cudaMalloc allowed): normalized codebook (packed f32 pairs)
// + |c|^2 per codeword.
__device__ unsigned long long g_codebook2[Hq * Sq * (Dq / 2)];  // 2 MB
__device__ float g_c2[Hq * Sq];                                 // 32 KB

// ---------------------------------------------------------------------------
// packed f32x2 helpers (Blackwell: 2 FP32 FMAs per issued instruction)
// ---------------------------------------------------------------------------
__device__ __forceinline__ unsigned long long pk2(float lo, float hi) {
    unsigned long long r;
    asm("mov.b64 %0, {%1, %2};" : "=l"(r) : "f"(lo), "f"(hi));
    return r;
}
__device__ __forceinline__ float2 upk2(unsigned long long v) {
    float2 f;
    asm("mov.b64 {%0, %1}, %2;" : "=f"(f.x), "=f"(f.y) : "l"(v));
    return f;
}
__device__ __forceinline__ unsigned long long ffma2(
    unsigned long long a, unsigned long long b, unsigned long long c) {
    unsigned long long d;
    asm("fma.rn.f32x2 %0, %1, %2, %3;" : "=l"(d) : "l"(a), "l"(b), "l"(c));
    return d;
}
__device__ __forceinline__ unsigned long long fadd2(
    unsigned long long a, unsigned long long b) {
    unsigned long long d;
    asm("add.rn.f32x2 %0, %1, %2;" : "=l"(d) : "l"(a), "l"(b));
    return d;
}

// ---------------------------------------------------------------------------
// Prep: c = c_sum / max(c_count, 1e-6); also |c|^2. One warp per codeword.
// Writes c to the 'c' output region and, packed, to the scratch codebook.
// A float2 {lo,hi} reinterpreted as u64 is exactly the f32x2 operand layout.
// ---------------------------------------------------------------------------
__global__ void prep_kernel(const float* __restrict__ c_sum,
                            const float* __restrict__ c_count,
                            float* __restrict__ out_c) {
    const int cw = blockIdx.x;        // h*S + s, 0..8191
    const int lane = threadIdx.x;     // 32 lanes, 2 dims each
    float cnt = fmaxf(c_count[cw], 1e-6f);

    const float2* src = (const float2*)(c_sum + (size_t)cw * Dq);
    float2 v = src[lane];
    float a = v.x / cnt;              // IEEE divide: matches reference exactly
    float b = v.y / cnt;
    ((float2*)(out_c + (size_t)cw * Dq))[lane] = make_float2(a, b);
    g_codebook2[(size_t)cw * (Dq / 2) + lane] = pk2(a, b);

    float sq = a * a + b * b;
    #pragma unroll
    for (int o = 16; o > 0; o >>= 1) sq += __shfl_xor_sync(0xFFFFFFFFu, sq, o);
    if (lane == 0) g_c2[cw] = sq;
}

// ---------------------------------------------------------------------------
// Main: each CTA = 256 rows of one (b,h); head codebook staged in smem as
// packed 64-bit pairs. One row per thread (argmin is thread-local).
// All lanes walk s together -> every LDS is a uniform-address broadcast
// (conflict-free, 16B/warp on the crossbar). One-hot epilogue written
// cooperatively (fully coalesced STG.128).
// ---------------------------------------------------------------------------
#define CB_U64 (Sq * Dq / 2)
#define SMEM_BYTES (CB_U64 * 8 + Sq * 4)

__global__ __launch_bounds__(256, 1)
void vq_kernel(const float* __restrict__ x, float* __restrict__ out) {
    extern __shared__ unsigned long long smem_u64[];
    unsigned long long* scb = smem_u64;            // [Sq*Dq/2] packed codebook
    float* sc2 = (float*)(smem_u64 + CB_U64);      // [Sq] |c|^2
    __shared__ int s_idx[256];

    const int bi   = blockIdx.x;       // 0..1023
    const int tile = bi & 15;          // 16 tiles of 256 rows per (b,h)
    const int bh   = bi >> 4;          // 0..63
    const int h    = bh & (Hq - 1);

    // Stage codebook (128 KB) + c2 (2 KB). L2-resident after first wave.
    {
        const ulonglong2* src =
            (const ulonglong2*)(g_codebook2 + (size_t)h * CB_U64);
        ulonglong2* dst = (ulonglong2*)scb;
        #pragma unroll 4
        for (int i = threadIdx.x; i < CB_U64 / 2; i += 256) dst[i] = src[i];
        for (int i = threadIdx.x; i < Sq; i += 256) sc2[i] = g_c2[h * Sq + i];
    }
    __syncthreads();

    const int rowbase = bh * Lq + tile * 256;     // global row in [B*H*L]
    const int row = rowbase + threadIdx.x;

    // Load this thread's x row (64 f32 = 32 packed pairs) into registers.
    unsigned long long xv[32];
    {
        const float4* xr = (const float4*)(x + (size_t)row * Dq);
        #pragma unroll
        for (int i = 0; i < 16; i++) {
            float4 v = xr[i];
            xv[2 * i]     = pk2(v.x, v.y);
            xv[2 * i + 1] = pk2(v.z, v.w);
        }
    }

    float best = 3.0e38f;
    int bidx = 0;
    const unsigned long long z2 = pk2(0.0f, 0.0f);

    #pragma unroll 2
    for (int s = 0; s < Sq; ++s) {
        const ulonglong2* cs = (const ulonglong2*)(scb + s * (Dq / 2));
        unsigned long long a0 = z2, a1 = z2, a2 = z2, a3 = z2;  // 4 dep chains
        #pragma unroll
        for (int i = 0; i < 8; i++) {
            ulonglong2 p0 = cs[2 * i];        // LDS.128 -> 2 packed operands
            ulonglong2 p1 = cs[2 * i + 1];
            a0 = ffma2(xv[4 * i + 0], p0.x, a0);
            a1 = ffma2(xv[4 * i + 1], p0.y, a1);
            a2 = ffma2(xv[4 * i + 2], p1.x, a2);
            a3 = ffma2(xv[4 * i + 3], p1.y, a3);
        }
        a0 = fadd2(a0, a2);
        a1 = fadd2(a1, a3);
        a0 = fadd2(a0, a1);
        float2 p = upk2(a0);
        float dot = p.x + p.y;
        float score = sc2[s] - 2.0f * dot;
        if (score < best) { best = score; bidx = s; }   // strict '<': first-min,
    }                                                    // matches jnp.argmin

    s_idx[threadIdx.x] = bidx;
    __syncthreads();

    // Cooperative one-hot write: 256 rows x 512 f32 = 32768 float4 quads,
    // 128 per thread, consecutive threads -> consecutive quads (coalesced).
    float4* ob4 = (float4*)(out + (size_t)rowbase * Sq);
    #pragma unroll 4
    for (int it = 0; it < 128; ++it) {
        int idx = it * 256 + (int)threadIdx.x;
        int r   = idx >> 7;        // quad / 128  -> local row
        int c4  = idx & 127;       // quad within row
        int b   = s_idx[r];
        int base = c4 << 2;
        float4 v;
        v.x = (b == base)     ? 1.0f : 0.0f;
        v.y = (b == base + 1) ? 1.0f : 0.0f;
        v.z = (b == base + 2) ? 1.0f : 0.0f;
        v.w = (b == base + 3) ? 1.0f : 0.0f;
        ob4[idx] = v;
    }
}

// ---------------------------------------------------------------------------
extern "C" void kernel_launch(void* const* d_in, const int* in_sizes, int n_in,
                              void* d_out, int out_size) {
    const float* x       = (const float*)d_in[0];
    const float* c_sum   = (const float*)d_in[1];
    const float* c_count = (const float*)d_in[2];
    float* out   = (float*)d_out;
    float* out_c = out + ONEHOT_ELEMS;   // 'c' follows the one-hot block

    (void)in_sizes; (void)n_in; (void)out_size;

    cudaFuncSetAttribute(vq_kernel,
                         cudaFuncAttributeMaxDynamicSharedMemorySize,
                         SMEM_BYTES);

    prep_kernel<<<Hq * Sq, 32>>>(c_sum, c_count, out_c);
    vq_kernel<<<(Bq * Hq * Lq) / 256, 256, SMEM_BYTES>>>(x, out);
}

// round 4
// speedup vs baseline: 1.1983x; 1.1983x over previous
#include <cuda_runtime.h>
#include <cstdint>

// Quantizer — VQ assignment. B=4,H=16,L=4096,D=64,S=512.
//   out = [delta_onehot [B,H,L,S] f32 | c [H,S,D] f32]
// argmin_s(|x|^2 - 2x.c + |c|^2) == argmin_s(|c|^2 - 2x.c)  (monotone shift).
//
// R2 -> R3 change: register-block 2 rows per thread so each codebook LDS.128
// feeds 2x the FFMA2s (ncu showed L1=80% saturated, fma only 42%).
// (R3 bench was an infra flake; resubmitting unchanged.)

#define Bq 4
#define Hq 16
#define Lq 4096
#define Dq 64
#define Sq 512

#define ONEHOT_ELEMS ((size_t)Bq * Hq * Lq * Sq)

__device__ unsigned long long g_codebook2[Hq * Sq * (Dq / 2)];  // 2 MB packed
__device__ float g_c2[Hq * Sq];                                 // 32 KB

// ---------------- packed f32x2 helpers ----------------
__device__ __forceinline__ unsigned long long pk2(float lo, float hi) {
    unsigned long long r;
    asm("mov.b64 %0, {%1, %2};" : "=l"(r) : "f"(lo), "f"(hi));
    return r;
}
__device__ __forceinline__ float2 upk2(unsigned long long v) {
    float2 f;
    asm("mov.b64 {%0, %1}, %2;" : "=f"(f.x), "=f"(f.y) : "l"(v));
    return f;
}
__device__ __forceinline__ unsigned long long ffma2(
    unsigned long long a, unsigned long long b, unsigned long long c) {
    unsigned long long d;
    asm("fma.rn.f32x2 %0, %1, %2, %3;" : "=l"(d) : "l"(a), "l"(b), "l"(c));
    return d;
}
__device__ __forceinline__ unsigned long long fadd2(
    unsigned long long a, unsigned long long b) {
    unsigned long long d;
    asm("add.rn.f32x2 %0, %1, %2;" : "=l"(d) : "l"(a), "l"(b));
    return d;
}

// ---------------- prep: c = c_sum / max(count,1e-6), |c|^2 ----------------
__global__ void prep_kernel(const float* __restrict__ c_sum,
                            const float* __restrict__ c_count,
                            float* __restrict__ out_c) {
    const int cw = blockIdx.x;        // h*S + s
    const int lane = threadIdx.x;     // 32 lanes, 2 dims each
    float cnt = fmaxf(c_count[cw], 1e-6f);

    const float2* src = (const float2*)(c_sum + (size_t)cw * Dq);
    float2 v = src[lane];
    float a = v.x / cnt;              // IEEE divide: bit-exact vs reference
    float b = v.y / cnt;
    ((float2*)(out_c + (size_t)cw * Dq))[lane] = make_float2(a, b);
    g_codebook2[(size_t)cw * (Dq / 2) + lane] = pk2(a, b);

    float sq = a * a + b * b;
    #pragma unroll
    for (int o = 16; o > 0; o >>= 1) sq += __shfl_xor_sync(0xFFFFFFFFu, sq, o);
    if (lane == 0) g_c2[cw] = sq;
}

// ---------------- main ----------------
// CTA: 256 threads, 2 rows/thread => 512 rows of one (b,h). Head codebook
// (128KB, packed u64 pairs) in smem; every LDS is a uniform broadcast.
#define ROWS_PER_CTA 512
#define CB_U64 (Sq * Dq / 2)
#define SMEM_BYTES (CB_U64 * 8 + Sq * 4)

__global__ __launch_bounds__(256, 1)
void vq_kernel(const float* __restrict__ x, float* __restrict__ out) {
    extern __shared__ unsigned long long smem_u64[];
    unsigned long long* scb = smem_u64;            // [Sq*Dq/2]
    float* sc2 = (float*)(smem_u64 + CB_U64);      // [Sq]
    __shared__ int s_idx[ROWS_PER_CTA];

    const int bi   = blockIdx.x;       // 0..511
    const int tile = bi & 7;           // 8 tiles of 512 rows per (b,h)
    const int bh   = bi >> 3;          // 0..63
    const int h    = bh & (Hq - 1);

    // Stage codebook + c2 (L2-resident after wave 1).
    {
        const ulonglong2* src =
            (const ulonglong2*)(g_codebook2 + (size_t)h * CB_U64);
        ulonglong2* dst = (ulonglong2*)scb;
        #pragma unroll 4
        for (int i = threadIdx.x; i < CB_U64 / 2; i += 256) dst[i] = src[i];
        for (int i = threadIdx.x; i < Sq; i += 256) sc2[i] = g_c2[h * Sq + i];
    }
    __syncthreads();

    const int rowbase = bh * Lq + tile * ROWS_PER_CTA;
    const int r0 = rowbase + threadIdx.x;          // rows split stride-256:
    const int r1 = r0 + 256;                       // keeps x loads coalesced

    // Two x rows in packed registers: 2 x 32 u64 = 128 regs.
    unsigned long long xa[32], xb[32];
    {
        const float4* p0 = (const float4*)(x + (size_t)r0 * Dq);
        const float4* p1 = (const float4*)(x + (size_t)r1 * Dq);
        #pragma unroll
        for (int i = 0; i < 16; i++) {
            float4 v0 = p0[i];
            float4 v1 = p1[i];
            xa[2 * i]     = pk2(v0.x, v0.y);
            xa[2 * i + 1] = pk2(v0.z, v0.w);
            xb[2 * i]     = pk2(v1.x, v1.y);
            xb[2 * i + 1] = pk2(v1.z, v1.w);
        }
    }

    float best0 = 3.0e38f, best1 = 3.0e38f;
    int bidx0 = 0, bidx1 = 0;
    const unsigned long long z2 = pk2(0.0f, 0.0f);

    for (int s = 0; s < Sq; ++s) {
        const ulonglong2* cs = (const ulonglong2*)(scb + s * (Dq / 2));
        // 2 chains per row (4 independent chains total: lat-4/rt-2 covered).
        unsigned long long a0 = z2, a1 = z2, b0 = z2, b1 = z2;
        #pragma unroll
        for (int i = 0; i < 8; i++) {
            ulonglong2 q0 = cs[2 * i];        // LDS.128 -> 2 packed operands
            ulonglong2 q1 = cs[2 * i + 1];    // each load feeds BOTH rows
            a0 = ffma2(xa[4 * i + 0], q0.x, a0);
            b0 = ffma2(xb[4 * i + 0], q0.x, b0);
            a1 = ffma2(xa[4 * i + 1], q0.y, a1);
            b1 = ffma2(xb[4 * i + 1], q0.y, b1);
            a0 = ffma2(xa[4 * i + 2], q1.x, a0);
            b0 = ffma2(xb[4 * i + 2], q1.x, b0);
            a1 = ffma2(xa[4 * i + 3], q1.y, a1);
            b1 = ffma2(xb[4 * i + 3], q1.y, b1);
        }
        float c2s = sc2[s];
        a0 = fadd2(a0, a1);
        b0 = fadd2(b0, b1);
        float2 pa = upk2(a0);
        float2 pb = upk2(b0);
        float sc0 = c2s - 2.0f * (pa.x + pa.y);
        float sc1 = c2s - 2.0f * (pb.x + pb.y);
        if (sc0 < best0) { best0 = sc0; bidx0 = s; }  // strict '<' = first-min
        if (sc1 < best1) { best1 = sc1; bidx1 = s; }  // (jnp.argmin semantics)
    }

    s_idx[threadIdx.x]       = bidx0;
    s_idx[threadIdx.x + 256] = bidx1;
    __syncthreads();

    // Cooperative one-hot: 512 rows x 128 quads = 65536 float4, 256/thread,
    // consecutive threads -> consecutive quads (fully coalesced STG.128).
    float4* ob4 = (float4*)(out + (size_t)rowbase * Sq);
    #pragma unroll 4
    for (int it = 0; it < 256; ++it) {
        int idx = it * 256 + (int)threadIdx.x;
        int r   = idx >> 7;        // local row
        int c4  = idx & 127;       // quad within row
        int b   = s_idx[r];
        int base = c4 << 2;
        float4 v;
        v.x = (b == base)     ? 1.0f : 0.0f;
        v.y = (b == base + 1) ? 1.0f : 0.0f;
        v.z = (b == base + 2) ? 1.0f : 0.0f;
        v.w = (b == base + 3) ? 1.0f : 0.0f;
        ob4[idx] = v;
    }
}

// ---------------------------------------------------------------------------
extern "C" void kernel_launch(void* const* d_in, const int* in_sizes, int n_in,
                              void* d_out, int out_size) {
    const float* x       = (const float*)d_in[0];
    const float* c_sum   = (const float*)d_in[1];
    const float* c_count = (const float*)d_in[2];
    float* out   = (float*)d_out;
    float* out_c = out + ONEHOT_ELEMS;

    (void)in_sizes; (void)n_in; (void)out_size;

    cudaFuncSetAttribute(vq_kernel,
                         cudaFuncAttributeMaxDynamicSharedMemorySize,
                         SMEM_BYTES);

    prep_kernel<<<Hq * Sq, 32>>>(c_sum, c_count, out_c);
    vq_kernel<<<(Bq * Hq * Lq) / ROWS_PER_CTA, 256, SMEM_BYTES>>>(x, out);
}

// round 6
// speedup vs baseline: 1.5735x; 1.3131x over previous
#include <cuda_runtime.h>
#include <cstdint>

// Quantizer — VQ assignment via mma.sync tf32 4-term split (sm_100-safe PTX).
//   x [B,H,L,D] f32, c_sum [H,S,D] f32, c_count [H,S] f32
//   out = [delta_onehot [B,H,L,S] f32 | c [H,S,D] f32]
// score_s = |c_s|^2 + x.(-2 c_s); 4-term tf32 split (hi+lo on both sides)
// with fp32 accumulate: residual ~1e-9 << argmin gaps -> no argmin flips.

#define Bq 4
#define Hq 16
#define Lq 4096
#define Dq 64
#define Sq 512
#define ONEHOT_ELEMS ((size_t)Bq * Hq * Lq * Sq)

// Codebook scratch: per (h,s) row of 128 floats: [-2c hi (64) | -2c lo (64)],
// k-permuted so mma B-fragment pairs (k, k+4) are adjacent (one LDS.64).
__device__ float g_cbB[Hq * Sq * 128];   // 4 MB
__device__ float g_c2[Hq * Sq];          // 32 KB

// -------------------- helpers --------------------
__device__ __forceinline__ uint32_t smem_u32(const void* p) {
    uint32_t a;
    asm("{ .reg .u64 t; cvta.to.shared.u64 t, %1; cvt.u32.u64 %0, t; }"
        : "=r"(a) : "l"(p));
    return a;
}
__device__ __forceinline__ float to_tf32(float x) {
    uint32_t u;
    asm("cvt.rna.tf32.f32 %0, %1;" : "=r"(u) : "f"(x));
    return __uint_as_float(u);
}
__device__ __forceinline__ void cp16(uint32_t s, const void* g) {
    asm volatile("cp.async.ca.shared.global [%0], [%1], 16;" :: "r"(s), "l"(g));
}
#define CP_COMMIT() asm volatile("cp.async.commit_group;" ::: "memory")
#define CP_WAIT0()  asm volatile("cp.async.wait_group 0;" ::: "memory")

// m16n8k8 tf32: a = {A[g][m],A[g+8][m],A[g][m+4],A[g+8][m+4]},
// b = {B[m][g],B[m+4][g]}, d = {D[g][2m],D[g][2m+1],D[g+8][2m],D[g+8][2m+1]}.
__device__ __forceinline__ void mma1688(float4& d, float2 a0, float2 a1, float2 b) {
    asm("mma.sync.aligned.m16n8k8.row.col.f32.tf32.tf32.f32 "
        "{%0,%1,%2,%3}, {%4,%5,%6,%7}, {%8,%9}, {%0,%1,%2,%3};"
        : "+f"(d.x), "+f"(d.y), "+f"(d.z), "+f"(d.w)
        : "r"(__float_as_uint(a0.x)), "r"(__float_as_uint(a1.x)),
          "r"(__float_as_uint(a0.y)), "r"(__float_as_uint(a1.y)),
          "r"(__float_as_uint(b.x)),  "r"(__float_as_uint(b.y)));
}

// k-permutation: pos(k) puts (m, m+4) adjacent within each 8-block.
__device__ __forceinline__ int kpos(int k) {
    return (k & ~7) + ((k & 3) << 1) + ((k >> 2) & 1);
}

// -------------------- prep --------------------
__global__ void prep_kernel(const float* __restrict__ c_sum,
                            const float* __restrict__ c_count,
                            float* __restrict__ out_c) {
    const int cw = blockIdx.x;        // h*S + s
    const int lane = threadIdx.x;     // 2 dims per lane
    float cnt = fmaxf(c_count[cw], 1e-6f);

    float2 v = ((const float2*)(c_sum + (size_t)cw * Dq))[lane];
    float a = v.x / cnt;              // IEEE divide: matches reference
    float b = v.y / cnt;
    ((float2*)(out_c + (size_t)cw * Dq))[lane] = make_float2(a, b);

    float* row = g_cbB + (size_t)cw * 128;
    int k0 = 2 * lane, k1 = 2 * lane + 1;
    float m0 = -2.0f * a, m1 = -2.0f * b;
    float h0 = to_tf32(m0), h1 = to_tf32(m1);
    row[kpos(k0)]      = h0;
    row[kpos(k1)]      = h1;
    row[64 + kpos(k0)] = to_tf32(m0 - h0);
    row[64 + kpos(k1)] = to_tf32(m1 - h1);

    float sq = a * a + b * b;
    #pragma unroll
    for (int o = 16; o > 0; o >>= 1) sq += __shfl_xor_sync(0xFFFFFFFFu, sq, o);
    if (lane == 0) g_c2[cw] = sq;
}

// -------------------- main --------------------
// CTA: 256 threads, 256 rows. Warp tile M=32 (2 x m16), A hi/lo in registers,
// B streamed 16-codeword chunks via cp.async double buffer.
#define ROWS 256
#define RSTRIDE 136                   // padded row (floats): banks 8-shift/row
#define A_F     0                     // A: 256*136 floats
#define B0_F    (ROWS * RSTRIDE)      // 34816
#define B1_F    (B0_F + 16 * RSTRIDE) // 36992
#define C2_F    (B1_F + 16 * RSTRIDE) // 39168
#define IDX_F   (C2_F + Sq)           // 39680
#define SMEM_TOTAL ((IDX_F + ROWS) * 4)

__global__ __launch_bounds__(256, 1)
void vq_kernel(const float* __restrict__ x, float* __restrict__ out) {
    extern __shared__ float sm[];
    const uint32_t sb = smem_u32(sm);
    const int tid = threadIdx.x;
    const int wid = tid >> 5, lane = tid & 31;
    const int g = lane >> 2, m = lane & 3;
    const int wb = wid * 32;

    const int rowbase = blockIdx.x * ROWS;
    const int h = (blockIdx.x >> 4) & (Hq - 1);   // 16 CTAs per (b,h)
    const float* cbh = g_cbB + (size_t)h * Sq * 128;

    // Prefetch B chunk 0 (16 codewords x 128 floats, rows padded to 136).
    for (int i = tid; i < 512; i += 256) {
        int r = i >> 5, q = i & 31;
        cp16(sb + (B0_F + r * RSTRIDE) * 4 + q * 16, (const char*)cbh + i * 16);
    }
    CP_COMMIT();

    // Stage c2 + A tile (hi/lo tf32, k-permuted, padded rows).
    for (int i = tid; i < Sq; i += 256) sm[C2_F + i] = g_c2[h * Sq + i];
    {
        const float4* xb = (const float4*)(x + (size_t)rowbase * Dq);
        #pragma unroll
        for (int it = 0; it < 8; ++it) {
            int i = it * 256 + tid;           // 256 rows x 8 kblocks
            int r = i >> 3, kb = i & 7;
            float4 v0 = xb[r * 16 + kb * 2];
            float4 v1 = xb[r * 16 + kb * 2 + 1];
            float h0 = to_tf32(v0.x), h1 = to_tf32(v0.y),
                  h2 = to_tf32(v0.z), h3 = to_tf32(v0.w),
                  h4 = to_tf32(v1.x), h5 = to_tf32(v1.y),
                  h6 = to_tf32(v1.z), h7 = to_tf32(v1.w);
            float l0 = to_tf32(v0.x - h0), l1 = to_tf32(v0.y - h1),
                  l2 = to_tf32(v0.z - h2), l3 = to_tf32(v0.w - h3),
                  l4 = to_tf32(v1.x - h4), l5 = to_tf32(v1.y - h5),
                  l6 = to_tf32(v1.z - h6), l7 = to_tf32(v1.w - h7);
            float* dh = sm + A_F + r * RSTRIDE + kb * 8;
            // permuted order within 8-block: {k0,k4,k1,k5},{k2,k6,k3,k7}
            ((float4*)dh)[0] = make_float4(h0, h4, h1, h5);
            ((float4*)dh)[1] = make_float4(h2, h6, h3, h7);
            float* dl = dh + 64;
            ((float4*)dl)[0] = make_float4(l0, l4, l1, l5);
            ((float4*)dl)[1] = make_float4(l2, l6, l3, l7);
        }
    }
    CP_WAIT0();
    __syncthreads();

    // A fragments to registers: [tile][kblock][row-half], hi and lo.
    float2 Ah[2][8][2], Al[2][8][2];
    #pragma unroll
    for (int t = 0; t < 2; ++t)
        #pragma unroll
        for (int kb = 0; kb < 8; ++kb) {
            int r0 = wb + t * 16 + g;
            const float* b0 = sm + A_F + r0 * RSTRIDE + kb * 8 + m * 2;
            const float* b8 = b0 + 8 * RSTRIDE;
            Ah[t][kb][0] = *(const float2*)b0;
            Ah[t][kb][1] = *(const float2*)b8;
            Al[t][kb][0] = *(const float2*)(b0 + 64);
            Al[t][kb][1] = *(const float2*)(b8 + 64);
        }

    float best[4] = {3.0e38f, 3.0e38f, 3.0e38f, 3.0e38f};
    int bidx[4] = {0, 0, 0, 0};

    for (int nch = 0; nch < 32; ++nch) {
        const float* Bbuf = sm + ((nch & 1) ? B1_F : B0_F);
        if (nch < 31) {
            const char* src = (const char*)(cbh + (size_t)(nch + 1) * 16 * 128);
            uint32_t dstb = sb + ((nch & 1) ? B0_F : B1_F) * 4;
            for (int i = tid; i < 512; i += 256) {
                int r = i >> 5, q = i & 31;
                cp16(dstb + (r * RSTRIDE) * 4 + q * 16, src + i * 16);
            }
            CP_COMMIT();
        }

        float4 acc[2][2];                 // [colblock][tile]
        #pragma unroll
        for (int cb = 0; cb < 2; ++cb) {
            float2 cv = *(const float2*)(sm + C2_F + nch * 16 + cb * 8 + m * 2);
            #pragma unroll
            for (int t = 0; t < 2; ++t)
                acc[cb][t] = make_float4(cv.x, cv.y, cv.x, cv.y);
        }

        #pragma unroll
        for (int cb = 0; cb < 2; ++cb) {
            const float* bn = Bbuf + (cb * 8 + g) * RSTRIDE + m * 2;
            #pragma unroll
            for (int kb = 0; kb < 8; ++kb) {
                float2 bh = *(const float2*)(bn + kb * 8);        // -2c hi
                float2 bl = *(const float2*)(bn + 64 + kb * 8);   // -2c lo
                mma1688(acc[cb][0], Ah[0][kb][0], Ah[0][kb][1], bh);
                mma1688(acc[cb][1], Ah[1][kb][0], Ah[1][kb][1], bh);
                mma1688(acc[cb][0], Al[0][kb][0], Al[0][kb][1], bh);
                mma1688(acc[cb][1], Al[1][kb][0], Al[1][kb][1], bh);
                mma1688(acc[cb][0], Ah[0][kb][0], Ah[0][kb][1], bl);
                mma1688(acc[cb][1], Ah[1][kb][0], Ah[1][kb][1], bl);
                mma1688(acc[cb][0], Al[0][kb][0], Al[0][kb][1], bl);
                mma1688(acc[cb][1], Al[1][kb][0], Al[1][kb][1], bl);
            }
        }

        // Argmin update (ascending n, strict '<' => first-min like jnp.argmin).
        #pragma unroll
        for (int cb = 0; cb < 2; ++cb) {
            int n0 = nch * 16 + cb * 8 + m * 2;
            #pragma unroll
            for (int t = 0; t < 2; ++t) {
                int s0 = t * 2, s1 = t * 2 + 1;       // rows g, g+8 (per tile)
                float4 a = acc[cb][t];
                if (a.x < best[s0]) { best[s0] = a.x; bidx[s0] = n0; }
                if (a.y < best[s0]) { best[s0] = a.y; bidx[s0] = n0 + 1; }
                if (a.z < best[s1]) { best[s1] = a.z; bidx[s1] = n0; }
                if (a.w < best[s1]) { best[s1] = a.w; bidx[s1] = n0 + 1; }
            }
        }

        CP_WAIT0();
        __syncthreads();
    }

    // Reduce across the 4 lanes (m) sharing each row; tie -> smaller index.
    #pragma unroll
    for (int s = 0; s < 4; ++s) {
        #pragma unroll
        for (int o = 1; o <= 2; o <<= 1) {
            float ob = __shfl_xor_sync(0xFFFFFFFFu, best[s], o);
            int   oi = __shfl_xor_sync(0xFFFFFFFFu, bidx[s], o);
            if (ob < best[s] || (ob == best[s] && oi < bidx[s])) {
                best[s] = ob; bidx[s] = oi;
            }
        }
    }
    if (m == 0) {
        int* si = (int*)(sm + IDX_F);
        si[wb + g]          = bidx[0];
        si[wb + g + 8]      = bidx[1];
        si[wb + 16 + g]     = bidx[2];
        si[wb + 16 + g + 8] = bidx[3];
    }
    __syncthreads();

    // Cooperative one-hot: 256 rows x 128 quads, coalesced STG.128.
    const int* si = (const int*)(sm + IDX_F);
    float4* ob4 = (float4*)(out + (size_t)rowbase * Sq);
    #pragma unroll 4
    for (int it = 0; it < 128; ++it) {
        int idx = it * 256 + tid;
        int r = idx >> 7, c4 = idx & 127;
        int b = si[r];
        int base = c4 << 2;
        float4 v;
        v.x = (b == base)     ? 1.0f : 0.0f;
        v.y = (b == base + 1) ? 1.0f : 0.0f;
        v.z = (b == base + 2) ? 1.0f : 0.0f;
        v.w = (b == base + 3) ? 1.0f : 0.0f;
        ob4[idx] = v;
    }
}

// ---------------------------------------------------------------------------
extern "C" void kernel_launch(void* const* d_in, const int* in_sizes, int n_in,
                              void* d_out, int out_size) {
    const float* x       = (const float*)d_in[0];
    const float* c_sum   = (const float*)d_in[1];
    const float* c_count = (const float*)d_in[2];
    float* out   = (float*)d_out;
    float* out_c = out + ONEHOT_ELEMS;

    (void)in_sizes; (void)n_in; (void)out_size;

    cudaFuncSetAttribute(vq_kernel,
                         cudaFuncAttributeMaxDynamicSharedMemorySize,
                         SMEM_TOTAL);

    prep_kernel<<<Hq * Sq, 32>>>(c_sum, c_count, out_c);
    vq_kernel<<<(Bq * Hq * Lq) / ROWS, 256, SMEM_TOTAL>>>(x, out);
}

// round 7
// speedup vs baseline: 1.8457x; 1.1730x over previous
#include <cuda_runtime.h>
#include <cstdint>

// Quantizer — VQ assignment via mma.sync tf32 3-term split (sm_100-safe PTX).
//   x [B,H,L,D] f32, c_sum [H,S,D] f32, c_count [H,S] f32
//   out = [delta_onehot [B,H,L,S] f32 | c [H,S,D] f32]
// score_s = |c_s|^2 + x.(-2 c_s).
// 3-term tf32 split (hi*hi + hi*lo + lo*hi, fp32 accumulate): residual
// ~2^-24 * |x.c| == plain-fp32-FFMA rounding class, which measured ZERO
// argmin flips in R2. R6->R7: drop lo*lo term (25% less MMA) + interleave
// all 4 accumulator chains per kb (tensor was 61% w/ issue 21% = dep stalls).

#define Bq 4
#define Hq 16
#define Lq 4096
#define Dq 64
#define Sq 512
#define ONEHOT_ELEMS ((size_t)Bq * Hq * Lq * Sq)

// Codebook scratch: per (h,s) row of 128 floats: [-2c hi (64) | -2c lo (64)],
// k-permuted so mma B-fragment pairs (k, k+4) are adjacent (one LDS.64).
__device__ float g_cbB[Hq * Sq * 128];   // 4 MB
__device__ float g_c2[Hq * Sq];          // 32 KB

// -------------------- helpers --------------------
__device__ __forceinline__ uint32_t smem_u32(const void* p) {
    uint32_t a;
    asm("{ .reg .u64 t; cvta.to.shared.u64 t, %1; cvt.u32.u64 %0, t; }"
        : "=r"(a) : "l"(p));
    return a;
}
__device__ __forceinline__ float to_tf32(float x) {
    uint32_t u;
    asm("cvt.rna.tf32.f32 %0, %1;" : "=r"(u) : "f"(x));
    return __uint_as_float(u);
}
__device__ __forceinline__ void cp16(uint32_t s, const void* g) {
    asm volatile("cp.async.ca.shared.global [%0], [%1], 16;" :: "r"(s), "l"(g));
}
#define CP_COMMIT() asm volatile("cp.async.commit_group;" ::: "memory")
#define CP_WAIT0()  asm volatile("cp.async.wait_group 0;" ::: "memory")

// m16n8k8 tf32 row.col; layout verified correct in R6 (rel_err 0.0).
__device__ __forceinline__ void mma1688(float4& d, float2 a0, float2 a1, float2 b) {
    asm("mma.sync.aligned.m16n8k8.row.col.f32.tf32.tf32.f32 "
        "{%0,%1,%2,%3}, {%4,%5,%6,%7}, {%8,%9}, {%0,%1,%2,%3};"
        : "+f"(d.x), "+f"(d.y), "+f"(d.z), "+f"(d.w)
        : "r"(__float_as_uint(a0.x)), "r"(__float_as_uint(a1.x)),
          "r"(__float_as_uint(a0.y)), "r"(__float_as_uint(a1.y)),
          "r"(__float_as_uint(b.x)),  "r"(__float_as_uint(b.y)));
}

// k-permutation: pos(k) puts (m, m+4) adjacent within each 8-block.
__device__ __forceinline__ int kpos(int k) {
    return (k & ~7) + ((k & 3) << 1) + ((k >> 2) & 1);
}

// -------------------- prep --------------------
__global__ void prep_kernel(const float* __restrict__ c_sum,
                            const float* __restrict__ c_count,
                            float* __restrict__ out_c) {
    const int cw = blockIdx.x;        // h*S + s
    const int lane = threadIdx.x;     // 2 dims per lane
    float cnt = fmaxf(c_count[cw], 1e-6f);

    float2 v = ((const float2*)(c_sum + (size_t)cw * Dq))[lane];
    float a = v.x / cnt;              // IEEE divide: matches reference
    float b = v.y / cnt;
    ((float2*)(out_c + (size_t)cw * Dq))[lane] = make_float2(a, b);

    float* row = g_cbB + (size_t)cw * 128;
    int k0 = 2 * lane, k1 = 2 * lane + 1;
    float m0 = -2.0f * a, m1 = -2.0f * b;
    float h0 = to_tf32(m0), h1 = to_tf32(m1);
    row[kpos(k0)]      = h0;
    row[kpos(k1)]      = h1;
    row[64 + kpos(k0)] = to_tf32(m0 - h0);
    row[64 + kpos(k1)] = to_tf32(m1 - h1);

    float sq = a * a + b * b;
    #pragma unroll
    for (int o = 16; o > 0; o >>= 1) sq += __shfl_xor_sync(0xFFFFFFFFu, sq, o);
    if (lane == 0) g_c2[cw] = sq;
}

// -------------------- main --------------------
// CTA: 256 threads, 256 rows. Warp tile M=32 (2 x m16), A hi/lo in registers,
// B streamed 16-codeword chunks via cp.async double buffer.
#define ROWS 256
#define RSTRIDE 136                   // padded row (floats)
#define A_F     0                     // A: 256*136 floats
#define B0_F    (ROWS * RSTRIDE)      // 34816
#define B1_F    (B0_F + 16 * RSTRIDE) // 36992
#define C2_F    (B1_F + 16 * RSTRIDE) // 39168
#define IDX_F   (C2_F + Sq)           // 39680
#define SMEM_TOTAL ((IDX_F + ROWS) * 4)

__global__ __launch_bounds__(256, 1)
void vq_kernel(const float* __restrict__ x, float* __restrict__ out) {
    extern __shared__ float sm[];
    const uint32_t sb = smem_u32(sm);
    const int tid = threadIdx.x;
    const int wid = tid >> 5, lane = tid & 31;
    const int g = lane >> 2, m = lane & 3;
    const int wb = wid * 32;

    const int rowbase = blockIdx.x * ROWS;
    const int h = (blockIdx.x >> 4) & (Hq - 1);   // 16 CTAs per (b,h)
    const float* cbh = g_cbB + (size_t)h * Sq * 128;

    // Prefetch B chunk 0 (16 codewords x 128 floats, rows padded to 136).
    for (int i = tid; i < 512; i += 256) {
        int r = i >> 5, q = i & 31;
        cp16(sb + (B0_F + r * RSTRIDE) * 4 + q * 16, (const char*)cbh + i * 16);
    }
    CP_COMMIT();

    // Stage c2 + A tile (hi/lo tf32, k-permuted, padded rows).
    for (int i = tid; i < Sq; i += 256) sm[C2_F + i] = g_c2[h * Sq + i];
    {
        const float4* xb = (const float4*)(x + (size_t)rowbase * Dq);
        #pragma unroll
        for (int it = 0; it < 8; ++it) {
            int i = it * 256 + tid;           // 256 rows x 8 kblocks
            int r = i >> 3, kb = i & 7;
            float4 v0 = xb[r * 16 + kb * 2];
            float4 v1 = xb[r * 16 + kb * 2 + 1];
            float h0 = to_tf32(v0.x), h1 = to_tf32(v0.y),
                  h2 = to_tf32(v0.z), h3 = to_tf32(v0.w),
                  h4 = to_tf32(v1.x), h5 = to_tf32(v1.y),
                  h6 = to_tf32(v1.z), h7 = to_tf32(v1.w);
            float l0 = to_tf32(v0.x - h0), l1 = to_tf32(v0.y - h1),
                  l2 = to_tf32(v0.z - h2), l3 = to_tf32(v0.w - h3),
                  l4 = to_tf32(v1.x - h4), l5 = to_tf32(v1.y - h5),
                  l6 = to_tf32(v1.z - h6), l7 = to_tf32(v1.w - h7);
            float* dh = sm + A_F + r * RSTRIDE + kb * 8;
            // permuted order within 8-block: {k0,k4,k1,k5},{k2,k6,k3,k7}
            ((float4*)dh)[0] = make_float4(h0, h4, h1, h5);
            ((float4*)dh)[1] = make_float4(h2, h6, h3, h7);
            float* dl = dh + 64;
            ((float4*)dl)[0] = make_float4(l0, l4, l1, l5);
            ((float4*)dl)[1] = make_float4(l2, l6, l3, l7);
        }
    }
    CP_WAIT0();
    __syncthreads();

    // A fragments to registers: [tile][kblock][row-half], hi and lo.
    float2 Ah[2][8][2], Al[2][8][2];
    #pragma unroll
    for (int t = 0; t < 2; ++t)
        #pragma unroll
        for (int kb = 0; kb < 8; ++kb) {
            int r0 = wb + t * 16 + g;
            const float* b0 = sm + A_F + r0 * RSTRIDE + kb * 8 + m * 2;
            const float* b8 = b0 + 8 * RSTRIDE;
            Ah[t][kb][0] = *(const float2*)b0;
            Ah[t][kb][1] = *(const float2*)b8;
            Al[t][kb][0] = *(const float2*)(b0 + 64);
            Al[t][kb][1] = *(const float2*)(b8 + 64);
        }

    float best[4] = {3.0e38f, 3.0e38f, 3.0e38f, 3.0e38f};
    int bidx[4] = {0, 0, 0, 0};

    for (int nch = 0; nch < 32; ++nch) {
        const float* Bbuf = sm + ((nch & 1) ? B1_F : B0_F);
        if (nch < 31) {
            const char* src = (const char*)(cbh + (size_t)(nch + 1) * 16 * 128);
            uint32_t dstb = sb + ((nch & 1) ? B0_F : B1_F) * 4;
            for (int i = tid; i < 512; i += 256) {
                int r = i >> 5, q = i & 31;
                cp16(dstb + (r * RSTRIDE) * 4 + q * 16, src + i * 16);
            }
            CP_COMMIT();
        }

        float4 acc[2][2];                 // [colblock][tile] -> 4 indep chains
        #pragma unroll
        for (int cb = 0; cb < 2; ++cb) {
            float2 cv = *(const float2*)(sm + C2_F + nch * 16 + cb * 8 + m * 2);
            #pragma unroll
            for (int t = 0; t < 2; ++t)
                acc[cb][t] = make_float4(cv.x, cv.y, cv.x, cv.y);
        }

        // kb outermost; per kb load 4 B fragments, issue 12 MMAs round-robin
        // across the 4 accumulator chains (same-acc spacing = 4).
        const float* bn0 = Bbuf + g * RSTRIDE + m * 2;
        const float* bn1 = Bbuf + (8 + g) * RSTRIDE + m * 2;
        #pragma unroll
        for (int kb = 0; kb < 8; ++kb) {
            float2 bh0 = *(const float2*)(bn0 + kb * 8);        // -2c hi, cb0
            float2 bl0 = *(const float2*)(bn0 + 64 + kb * 8);   // -2c lo, cb0
            float2 bh1 = *(const float2*)(bn1 + kb * 8);        // -2c hi, cb1
            float2 bl1 = *(const float2*)(bn1 + 64 + kb * 8);   // -2c lo, cb1
            // term hi*hi
            mma1688(acc[0][0], Ah[0][kb][0], Ah[0][kb][1], bh0);
            mma1688(acc[0][1], Ah[1][kb][0], Ah[1][kb][1], bh0);
            mma1688(acc[1][0], Ah[0][kb][0], Ah[0][kb][1], bh1);
            mma1688(acc[1][1], Ah[1][kb][0], Ah[1][kb][1], bh1);
            // term lo*hi
            mma1688(acc[0][0], Al[0][kb][0], Al[0][kb][1], bh0);
            mma1688(acc[0][1], Al[1][kb][0], Al[1][kb][1], bh0);
            mma1688(acc[1][0], Al[0][kb][0], Al[0][kb][1], bh1);
            mma1688(acc[1][1], Al[1][kb][0], Al[1][kb][1], bh1);
            // term hi*lo
            mma1688(acc[0][0], Ah[0][kb][0], Ah[0][kb][1], bl0);
            mma1688(acc[0][1], Ah[1][kb][0], Ah[1][kb][1], bl0);
            mma1688(acc[1][0], Ah[0][kb][0], Ah[0][kb][1], bl1);
            mma1688(acc[1][1], Ah[1][kb][0], Ah[1][kb][1], bl1);
        }

        // Argmin update (ascending n, strict '<' => first-min like jnp.argmin).
        #pragma unroll
        for (int cb = 0; cb < 2; ++cb) {
            int n0 = nch * 16 + cb * 8 + m * 2;
            #pragma unroll
            for (int t = 0; t < 2; ++t) {
                int s0 = t * 2, s1 = t * 2 + 1;       // rows g, g+8 (per tile)
                float4 a = acc[cb][t];
                if (a.x < best[s0]) { best[s0] = a.x; bidx[s0] = n0; }
                if (a.y < best[s0]) { best[s0] = a.y; bidx[s0] = n0 + 1; }
                if (a.z < best[s1]) { best[s1] = a.z; bidx[s1] = n0; }
                if (a.w < best[s1]) { best[s1] = a.w; bidx[s1] = n0 + 1; }
            }
        }

        CP_WAIT0();
        __syncthreads();
    }

    // Reduce across the 4 lanes (m) sharing each row; tie -> smaller index.
    #pragma unroll
    for (int s = 0; s < 4; ++s) {
        #pragma unroll
        for (int o = 1; o <= 2; o <<= 1) {
            float ob = __shfl_xor_sync(0xFFFFFFFFu, best[s], o);
            int   oi = __shfl_xor_sync(0xFFFFFFFFu, bidx[s], o);
            if (ob < best[s] || (ob == best[s] && oi < bidx[s])) {
                best[s] = ob; bidx[s] = oi;
            }
        }
    }
    if (m == 0) {
        int* si = (int*)(sm + IDX_F);
        si[wb + g]          = bidx[0];
        si[wb + g + 8]      = bidx[1];
        si[wb + 16 + g]     = bidx[2];
        si[wb + 16 + g + 8] = bidx[3];
    }
    __syncthreads();

    // Cooperative one-hot: 256 rows x 128 quads, coalesced STG.128.
    const int* si = (const int*)(sm + IDX_F);
    float4* ob4 = (float4*)(out + (size_t)rowbase * Sq);
    #pragma unroll 4
    for (int it = 0; it < 128; ++it) {
        int idx = it * 256 + tid;
        int r = idx >> 7, c4 = idx & 127;
        int b = si[r];
        int base = c4 << 2;
        float4 v;
        v.x = (b == base)     ? 1.0f : 0.0f;
        v.y = (b == base + 1) ? 1.0f : 0.0f;
        v.z = (b == base + 2) ? 1.0f : 0.0f;
        v.w = (b == base + 3) ? 1.0f : 0.0f;
        ob4[idx] = v;
    }
}

// ---------------------------------------------------------------------------
extern "C" void kernel_launch(void* const* d_in, const int* in_sizes, int n_in,
                              void* d_out, int out_size) {
    const float* x       = (const float*)d_in[0];
    const float* c_sum   = (const float*)d_in[1];
    const float* c_count = (const float*)d_in[2];
    float* out   = (float*)d_out;
    float* out_c = out + ONEHOT_ELEMS;

    (void)in_sizes; (void)n_in; (void)out_size;

    cudaFuncSetAttribute(vq_kernel,
                         cudaFuncAttributeMaxDynamicSharedMemorySize,
                         SMEM_TOTAL);

    prep_kernel<<<Hq * Sq, 32>>>(c_sum, c_count, out_c);
    vq_kernel<<<(Bq * Hq * Lq) / ROWS, 256, SMEM_TOTAL>>>(x, out);
}

// round 8
// speedup vs baseline: 1.9658x; 1.0650x over previous
#include <cuda_runtime.h>
#include <cstdint>

// Quantizer — VQ assignment via mma.sync tf32 3-term split (sm_100-safe PTX).
//   x [B,H,L,D] f32, c_sum [H,S,D] f32, c_count [H,S] f32
//   out = [delta_onehot [B,H,L,S] f32 | c [H,S,D] f32]
// score_s = |c_s|^2 + x.(-2 c_s); 3-term tf32 split, fp32 accumulate
// (residual ~1e-5 << argmin gaps; rel_err measured 0.0 in R7).
// R7 -> R8: N-chunk 16 -> 32 codewords (halve per-chunk barrier/wait/issue
// overhead: tensor was 53.8% with issue 22.5%), 8 accumulator chains,
// hoisted cp.async addressing.

#define Bq 4
#define Hq 16
#define Lq 4096
#define Dq 64
#define Sq 512
#define ONEHOT_ELEMS ((size_t)Bq * Hq * Lq * Sq)

// Codebook scratch: per (h,s) row of 128 floats: [-2c hi (64) | -2c lo (64)],
// k-permuted so mma B-fragment pairs (k, k+4) are adjacent (one LDS.64).
__device__ float g_cbB[Hq * Sq * 128];   // 4 MB
__device__ float g_c2[Hq * Sq];          // 32 KB

// -------------------- helpers --------------------
__device__ __forceinline__ uint32_t smem_u32(const void* p) {
    uint32_t a;
    asm("{ .reg .u64 t; cvta.to.shared.u64 t, %1; cvt.u32.u64 %0, t; }"
        : "=r"(a) : "l"(p));
    return a;
}
__device__ __forceinline__ float to_tf32(float x) {
    uint32_t u;
    asm("cvt.rna.tf32.f32 %0, %1;" : "=r"(u) : "f"(x));
    return __uint_as_float(u);
}
__device__ __forceinline__ void cp16(uint32_t s, const void* g) {
    asm volatile("cp.async.ca.shared.global [%0], [%1], 16;" :: "r"(s), "l"(g));
}
#define CP_COMMIT() asm volatile("cp.async.commit_group;" ::: "memory")
#define CP_WAIT0()  asm volatile("cp.async.wait_group 0;" ::: "memory")

// m16n8k8 tf32 row.col; layout verified correct in R6/R7 (rel_err 0.0).
__device__ __forceinline__ void mma1688(float4& d, float2 a0, float2 a1, float2 b) {
    asm("mma.sync.aligned.m16n8k8.row.col.f32.tf32.tf32.f32 "
        "{%0,%1,%2,%3}, {%4,%5,%6,%7}, {%8,%9}, {%0,%1,%2,%3};"
        : "+f"(d.x), "+f"(d.y), "+f"(d.z), "+f"(d.w)
        : "r"(__float_as_uint(a0.x)), "r"(__float_as_uint(a1.x)),
          "r"(__float_as_uint(a0.y)), "r"(__float_as_uint(a1.y)),
          "r"(__float_as_uint(b.x)),  "r"(__float_as_uint(b.y)));
}

// k-permutation: pos(k) puts (m, m+4) adjacent within each 8-block.
__device__ __forceinline__ int kpos(int k) {
    return (k & ~7) + ((k & 3) << 1) + ((k >> 2) & 1);
}

// -------------------- prep --------------------
__global__ void prep_kernel(const float* __restrict__ c_sum,
                            const float* __restrict__ c_count,
                            float* __restrict__ out_c) {
    const int cw = blockIdx.x;        // h*S + s
    const int lane = threadIdx.x;     // 2 dims per lane
    float cnt = fmaxf(c_count[cw], 1e-6f);

    float2 v = ((const float2*)(c_sum + (size_t)cw * Dq))[lane];
    float a = v.x / cnt;              // IEEE divide: matches reference
    float b = v.y / cnt;
    ((float2*)(out_c + (size_t)cw * Dq))[lane] = make_float2(a, b);

    float* row = g_cbB + (size_t)cw * 128;
    int k0 = 2 * lane, k1 = 2 * lane + 1;
    float m0 = -2.0f * a, m1 = -2.0f * b;
    float h0 = to_tf32(m0), h1 = to_tf32(m1);
    row[kpos(k0)]      = h0;
    row[kpos(k1)]      = h1;
    row[64 + kpos(k0)] = to_tf32(m0 - h0);
    row[64 + kpos(k1)] = to_tf32(m1 - h1);

    float sq = a * a + b * b;
    #pragma unroll
    for (int o = 16; o > 0; o >>= 1) sq += __shfl_xor_sync(0xFFFFFFFFu, sq, o);
    if (lane == 0) g_c2[cw] = sq;
}

// -------------------- main --------------------
// CTA: 256 threads, 256 rows. Warp tile M=32 (2 x m16), A hi/lo in registers,
// B streamed in 32-codeword chunks via cp.async double buffer.
#define ROWS 256
#define CH   32                       // codewords per chunk
#define RSTRIDE 136                   // padded row (floats)
#define A_F     0                     // A: 256*136 floats
#define B0_F    (ROWS * RSTRIDE)      // 34816
#define B1_F    (B0_F + CH * RSTRIDE) // 39168
#define C2_F    (B1_F + CH * RSTRIDE) // 43520
#define IDX_F   (C2_F + Sq)           // 44032
#define SMEM_TOTAL ((IDX_F + ROWS) * 4)

__global__ __launch_bounds__(256, 1)
void vq_kernel(const float* __restrict__ x, float* __restrict__ out) {
    extern __shared__ float sm[];
    const uint32_t sb = smem_u32(sm);
    const int tid = threadIdx.x;
    const int wid = tid >> 5, lane = tid & 31;
    const int g = lane >> 2, m = lane & 3;
    const int wb = wid * 32;

    const int rowbase = blockIdx.x * ROWS;
    const int h = (blockIdx.x >> 4) & (Hq - 1);   // 16 CTAs per (b,h)
    const float* cbh = g_cbB + (size_t)h * Sq * 128;

    // Hoisted cp.async addressing: this thread copies 4 x 16B per chunk.
    // Chunk layout: CH(32) rows x 128 floats, rows padded to RSTRIDE.
    uint32_t cp_dst[4];
    uint32_t cp_src[4];
    #pragma unroll
    for (int j = 0; j < 4; ++j) {
        int i = j * 256 + tid;            // 0..1023 (16B units)
        int r = i >> 5, q = i & 31;
        cp_dst[j] = (uint32_t)((r * RSTRIDE + q * 4) * 4);  // byte off in buf
        cp_src[j] = (uint32_t)(i * 16);                     // byte off in chunk
    }
    const char* cb_bytes = (const char*)cbh;

    // Prefetch B chunk 0.
    #pragma unroll
    for (int j = 0; j < 4; ++j)
        cp16(sb + B0_F * 4 + cp_dst[j], cb_bytes + cp_src[j]);
    CP_COMMIT();

    // Stage c2 + A tile (hi/lo tf32, k-permuted, padded rows).
    for (int i = tid; i < Sq; i += 256) sm[C2_F + i] = g_c2[h * Sq + i];
    {
        const float4* xb = (const float4*)(x + (size_t)rowbase * Dq);
        #pragma unroll
        for (int it = 0; it < 8; ++it) {
            int i = it * 256 + tid;           // 256 rows x 8 kblocks
            int r = i >> 3, kb = i & 7;
            float4 v0 = xb[r * 16 + kb * 2];
            float4 v1 = xb[r * 16 + kb * 2 + 1];
            float h0 = to_tf32(v0.x), h1 = to_tf32(v0.y),
                  h2 = to_tf32(v0.z), h3 = to_tf32(v0.w),
                  h4 = to_tf32(v1.x), h5 = to_tf32(v1.y),
                  h6 = to_tf32(v1.z), h7 = to_tf32(v1.w);
            float l0 = to_tf32(v0.x - h0), l1 = to_tf32(v0.y - h1),
                  l2 = to_tf32(v0.z - h2), l3 = to_tf32(v0.w - h3),
                  l4 = to_tf32(v1.x - h4), l5 = to_tf32(v1.y - h5),
                  l6 = to_tf32(v1.z - h6), l7 = to_tf32(v1.w - h7);
            float* dh = sm + A_F + r * RSTRIDE + kb * 8;
            // permuted order within 8-block: {k0,k4,k1,k5},{k2,k6,k3,k7}
            ((float4*)dh)[0] = make_float4(h0, h4, h1, h5);
            ((float4*)dh)[1] = make_float4(h2, h6, h3, h7);
            float* dl = dh + 64;
            ((float4*)dl)[0] = make_float4(l0, l4, l1, l5);
            ((float4*)dl)[1] = make_float4(l2, l6, l3, l7);
        }
    }
    CP_WAIT0();
    __syncthreads();

    // A fragments to registers: [tile][kblock][row-half], hi and lo.
    float2 Ah[2][8][2], Al[2][8][2];
    #pragma unroll
    for (int t = 0; t < 2; ++t)
        #pragma unroll
        for (int kb = 0; kb < 8; ++kb) {
            int r0 = wb + t * 16 + g;
            const float* b0 = sm + A_F + r0 * RSTRIDE + kb * 8 + m * 2;
            const float* b8 = b0 + 8 * RSTRIDE;
            Ah[t][kb][0] = *(const float2*)b0;
            Ah[t][kb][1] = *(const float2*)b8;
            Al[t][kb][0] = *(const float2*)(b0 + 64);
            Al[t][kb][1] = *(const float2*)(b8 + 64);
        }

    float best[4] = {3.0e38f, 3.0e38f, 3.0e38f, 3.0e38f};
    int bidx[4] = {0, 0, 0, 0};

    for (int nch = 0; nch < Sq / CH; ++nch) {        // 16 chunks of 32
        const float* Bbuf = sm + ((nch & 1) ? B1_F : B0_F);
        if (nch < Sq / CH - 1) {
            const char* src = cb_bytes + (size_t)(nch + 1) * CH * 128 * 4;
            uint32_t dstb = sb + ((nch & 1) ? B0_F : B1_F) * 4;
            #pragma unroll
            for (int j = 0; j < 4; ++j)
                cp16(dstb + cp_dst[j], src + cp_src[j]);
            CP_COMMIT();
        }

        float4 acc[4][2];                 // [colblock][tile] -> 8 indep chains
        #pragma unroll
        for (int cb = 0; cb < 4; ++cb) {
            float2 cv = *(const float2*)(sm + C2_F + nch * CH + cb * 8 + m * 2);
            #pragma unroll
            for (int t = 0; t < 2; ++t)
                acc[cb][t] = make_float4(cv.x, cv.y, cv.x, cv.y);
        }

        // kb outermost; per kb load 8 B fragments, issue 24 MMAs round-robin
        // across the 8 accumulator chains (same-chain spacing = 8).
        const float* bn0 = Bbuf + g * RSTRIDE + m * 2;
        const float* bn1 = bn0 + 8 * RSTRIDE;
        const float* bn2 = bn0 + 16 * RSTRIDE;
        const float* bn3 = bn0 + 24 * RSTRIDE;
        #pragma unroll
        for (int kb = 0; kb < 8; ++kb) {
            float2 bh0 = *(const float2*)(bn0 + kb * 8);
            float2 bh1 = *(const float2*)(bn1 + kb * 8);
            float2 bh2 = *(const float2*)(bn2 + kb * 8);
            float2 bh3 = *(const float2*)(bn3 + kb * 8);
            float2 bl0 = *(const float2*)(bn0 + 64 + kb * 8);
            float2 bl1 = *(const float2*)(bn1 + 64 + kb * 8);
            float2 bl2 = *(const float2*)(bn2 + 64 + kb * 8);
            float2 bl3 = *(const float2*)(bn3 + 64 + kb * 8);
            // term hi*hi
            mma1688(acc[0][0], Ah[0][kb][0], Ah[0][kb][1], bh0);
            mma1688(acc[0][1], Ah[1][kb][0], Ah[1][kb][1], bh0);
            mma1688(acc[1][0], Ah[0][kb][0], Ah[0][kb][1], bh1);
            mma1688(acc[1][1], Ah[1][kb][0], Ah[1][kb][1], bh1);
            mma1688(acc[2][0], Ah[0][kb][0], Ah[0][kb][1], bh2);
            mma1688(acc[2][1], Ah[1][kb][0], Ah[1][kb][1], bh2);
            mma1688(acc[3][0], Ah[0][kb][0], Ah[0][kb][1], bh3);
            mma1688(acc[3][1], Ah[1][kb][0], Ah[1][kb][1], bh3);
            // term lo*hi
            mma1688(acc[0][0], Al[0][kb][0], Al[0][kb][1], bh0);
            mma1688(acc[0][1], Al[1][kb][0], Al[1][kb][1], bh0);
            mma1688(acc[1][0], Al[0][kb][0], Al[0][kb][1], bh1);
            mma1688(acc[1][1], Al[1][kb][0], Al[1][kb][1], bh1);
            mma1688(acc[2][0], Al[0][kb][0], Al[0][kb][1], bh2);
            mma1688(acc[2][1], Al[1][kb][0], Al[1][kb][1], bh2);
            mma1688(acc[3][0], Al[0][kb][0], Al[0][kb][1], bh3);
            mma1688(acc[3][1], Al[1][kb][0], Al[1][kb][1], bh3);
            // term hi*lo
            mma1688(acc[0][0], Ah[0][kb][0], Ah[0][kb][1], bl0);
            mma1688(acc[0][1], Ah[1][kb][0], Ah[1][kb][1], bl0);
            mma1688(acc[1][0], Ah[0][kb][0], Ah[0][kb][1], bl1);
            mma1688(acc[1][1], Ah[1][kb][0], Ah[1][kb][1], bl1);
            mma1688(acc[2][0], Ah[0][kb][0], Ah[0][kb][1], bl2);
            mma1688(acc[2][1], Ah[1][kb][0], Ah[1][kb][1], bl2);
            mma1688(acc[3][0], Ah[0][kb][0], Ah[0][kb][1], bl3);
            mma1688(acc[3][1], Ah[1][kb][0], Ah[1][kb][1], bl3);
        }

        // Argmin update (ascending n, strict '<' => first-min like jnp.argmin).
        #pragma unroll
        for (int cb = 0; cb < 4; ++cb) {
            int n0 = nch * CH + cb * 8 + m * 2;
            #pragma unroll
            for (int t = 0; t < 2; ++t) {
                int s0 = t * 2, s1 = t * 2 + 1;       // rows g, g+8 (per tile)
                float4 a = acc[cb][t];
                if (a.x < best[s0]) { best[s0] = a.x; bidx[s0] = n0; }
                if (a.y < best[s0]) { best[s0] = a.y; bidx[s0] = n0 + 1; }
                if (a.z < best[s1]) { best[s1] = a.z; bidx[s1] = n0; }
                if (a.w < best[s1]) { best[s1] = a.w; bidx[s1] = n0 + 1; }
            }
        }

        CP_WAIT0();
        __syncthreads();
    }

    // Reduce across the 4 lanes (m) sharing each row; tie -> smaller index.
    #pragma unroll
    for (int s = 0; s < 4; ++s) {
        #pragma unroll
        for (int o = 1; o <= 2; o <<= 1) {
            float ob = __shfl_xor_sync(0xFFFFFFFFu, best[s], o);
            int   oi = __shfl_xor_sync(0xFFFFFFFFu, bidx[s], o);
            if (ob < best[s] || (ob == best[s] && oi < bidx[s])) {
                best[s] = ob; bidx[s] = oi;
            }
        }
    }
    if (m == 0) {
        int* si = (int*)(sm + IDX_F);
        si[wb + g]          = bidx[0];
        si[wb + g + 8]      = bidx[1];
        si[wb + 16 + g]     = bidx[2];
        si[wb + 16 + g + 8] = bidx[3];
    }
    __syncthreads();

    // Cooperative one-hot: 256 rows x 128 quads, coalesced STG.128.
    const int* si = (const int*)(sm + IDX_F);
    float4* ob4 = (float4*)(out + (size_t)rowbase * Sq);
    #pragma unroll 4
    for (int it = 0; it < 128; ++it) {
        int idx = it * 256 + tid;
        int r = idx >> 7, c4 = idx & 127;
        int b = si[r];
        int base = c4 << 2;
        float4 v;
        v.x = (b == base)     ? 1.0f : 0.0f;
        v.y = (b == base + 1) ? 1.0f : 0.0f;
        v.z = (b == base + 2) ? 1.0f : 0.0f;
        v.w = (b == base + 3) ? 1.0f : 0.0f;
        ob4[idx] = v;
    }
}

// ---------------------------------------------------------------------------
extern "C" void kernel_launch(void* const* d_in, const int* in_sizes, int n_in,
                              void* d_out, int out_size) {
    const float* x       = (const float*)d_in[0];
    const float* c_sum   = (const float*)d_in[1];
    const float* c_count = (const float*)d_in[2];
    float* out   = (float*)d_out;
    float* out_c = out + ONEHOT_ELEMS;

    (void)in_sizes; (void)n_in; (void)out_size;

    cudaFuncSetAttribute(vq_kernel,
                         cudaFuncAttributeMaxDynamicSharedMemorySize,
                         SMEM_TOTAL);

    prep_kernel<<<Hq * Sq, 32>>>(c_sum, c_count, out_c);
    vq_kernel<<<(Bq * Hq * Lq) / ROWS, 256, SMEM_TOTAL>>>(x, out);
}

// round 9
// speedup vs baseline: 2.2892x; 1.1645x over previous
#include <cuda_runtime.h>
#include <cstdint>

// Quantizer — VQ assignment via mma.sync tf32 3-term split (sm_100-safe PTX).
//   x [B,H,L,D] f32, c_sum [H,S,D] f32, c_count [H,S] f32
//   out = [delta_onehot [B,H,L,S] f32 | c [H,S,D] f32]
// score_s = |c_s|^2 + x.(-2 c_s); 3-term tf32 split, fp32 accumulate
// (residual ~1e-5 << argmin gaps; rel_err measured 0.0 in R7/R8).
// R8 -> R9: 2 CTAs/SM (ROWS 256->128, threads 256->128) so one CTA's
// barrier/epilogue idle phases overlap the other's MMA phases (tensor was
// 57.6% with issue 22.5% at occ 12.5% -- serialized idle, not issue count).

#define Bq 4
#define Hq 16
#define Lq 4096
#define Dq 64
#define Sq 512
#define ONEHOT_ELEMS ((size_t)Bq * Hq * Lq * Sq)

// Codebook scratch: per (h,s) row of 128 floats: [-2c hi (64) | -2c lo (64)],
// k-permuted so mma B-fragment pairs (k, k+4) are adjacent (one LDS.64).
__device__ float g_cbB[Hq * Sq * 128];   // 4 MB
__device__ float g_c2[Hq * Sq];          // 32 KB

// -------------------- helpers --------------------
__device__ __forceinline__ uint32_t smem_u32(const void* p) {
    uint32_t a;
    asm("{ .reg .u64 t; cvta.to.shared.u64 t, %1; cvt.u32.u64 %0, t; }"
        : "=r"(a) : "l"(p));
    return a;
}
__device__ __forceinline__ float to_tf32(float x) {
    uint32_t u;
    asm("cvt.rna.tf32.f32 %0, %1;" : "=r"(u) : "f"(x));
    return __uint_as_float(u);
}
__device__ __forceinline__ void cp16(uint32_t s, const void* g) {
    asm volatile("cp.async.ca.shared.global [%0], [%1], 16;" :: "r"(s), "l"(g));
}
#define CP_COMMIT() asm volatile("cp.async.commit_group;" ::: "memory")
#define CP_WAIT0()  asm volatile("cp.async.wait_group 0;" ::: "memory")

// m16n8k8 tf32 row.col; layout verified correct in R6-R8 (rel_err 0.0).
__device__ __forceinline__ void mma1688(float4& d, float2 a0, float2 a1, float2 b) {
    asm("mma.sync.aligned.m16n8k8.row.col.f32.tf32.tf32.f32 "
        "{%0,%1,%2,%3}, {%4,%5,%6,%7}, {%8,%9}, {%0,%1,%2,%3};"
        : "+f"(d.x), "+f"(d.y), "+f"(d.z), "+f"(d.w)
        : "r"(__float_as_uint(a0.x)), "r"(__float_as_uint(a1.x)),
          "r"(__float_as_uint(a0.y)), "r"(__float_as_uint(a1.y)),
          "r"(__float_as_uint(b.x)),  "r"(__float_as_uint(b.y)));
}

// k-permutation: pos(k) puts (m, m+4) adjacent within each 8-block.
__device__ __forceinline__ int kpos(int k) {
    return (k & ~7) + ((k & 3) << 1) + ((k >> 2) & 1);
}

// -------------------- prep --------------------
__global__ void prep_kernel(const float* __restrict__ c_sum,
                            const float* __restrict__ c_count,
                            float* __restrict__ out_c) {
    const int cw = blockIdx.x;        // h*S + s
    const int lane = threadIdx.x;     // 2 dims per lane
    float cnt = fmaxf(c_count[cw], 1e-6f);

    float2 v = ((const float2*)(c_sum + (size_t)cw * Dq))[lane];
    float a = v.x / cnt;              // IEEE divide: matches reference
    float b = v.y / cnt;
    ((float2*)(out_c + (size_t)cw * Dq))[lane] = make_float2(a, b);

    float* row = g_cbB + (size_t)cw * 128;
    int k0 = 2 * lane, k1 = 2 * lane + 1;
    float m0 = -2.0f * a, m1 = -2.0f * b;
    float h0 = to_tf32(m0), h1 = to_tf32(m1);
    row[kpos(k0)]      = h0;
    row[kpos(k1)]      = h1;
    row[64 + kpos(k0)] = to_tf32(m0 - h0);
    row[64 + kpos(k1)] = to_tf32(m1 - h1);

    float sq = a * a + b * b;
    #pragma unroll
    for (int o = 16; o > 0; o >>= 1) sq += __shfl_xor_sync(0xFFFFFFFFu, sq, o);
    if (lane == 0) g_c2[cw] = sq;
}

// -------------------- main --------------------
// CTA: 128 threads (4 warps), 128 rows. Warp tile M=32 (2 x m16), A hi/lo in
// registers, B streamed in 32-codeword chunks via cp.async double buffer.
// 2 CTAs per SM.
#define ROWS 128
#define NTHR 128
#define CH   32                       // codewords per chunk
#define RSTRIDE 136                   // padded row (floats)
#define A_F     0                     // A: 128*136 floats
#define B0_F    (ROWS * RSTRIDE)      // 17408
#define B1_F    (B0_F + CH * RSTRIDE) // 21760
#define C2_F    (B1_F + CH * RSTRIDE) // 26112
#define IDX_F   (C2_F + Sq)           // 26624
#define SMEM_TOTAL ((IDX_F + ROWS) * 4)   // 107008 B -> 2 CTAs/SM

__global__ __launch_bounds__(NTHR, 2)
void vq_kernel(const float* __restrict__ x, float* __restrict__ out) {
    extern __shared__ float sm[];
    const uint32_t sb = smem_u32(sm);
    const int tid = threadIdx.x;
    const int wid = tid >> 5, lane = tid & 31;
    const int g = lane >> 2, m = lane & 3;
    const int wb = wid * 32;

    const int rowbase = blockIdx.x * ROWS;
    const int h = (blockIdx.x >> 5) & (Hq - 1);   // 32 CTAs per (b,h)
    const float* cbh = g_cbB + (size_t)h * Sq * 128;

    // Hoisted cp.async addressing: this thread copies 8 x 16B per chunk.
    // Chunk layout: CH(32) rows x 128 floats, rows padded to RSTRIDE.
    uint32_t cp_dst[8];
    uint32_t cp_src[8];
    #pragma unroll
    for (int j = 0; j < 8; ++j) {
        int i = j * NTHR + tid;           // 0..1023 (16B units)
        int r = i >> 5, q = i & 31;
        cp_dst[j] = (uint32_t)((r * RSTRIDE + q * 4) * 4);  // byte off in buf
        cp_src[j] = (uint32_t)(i * 16);                     // byte off in chunk
    }
    const char* cb_bytes = (const char*)cbh;

    // Prefetch B chunk 0.
    #pragma unroll
    for (int j = 0; j < 8; ++j)
        cp16(sb + B0_F * 4 + cp_dst[j], cb_bytes + cp_src[j]);
    CP_COMMIT();

    // Stage c2 + A tile (hi/lo tf32, k-permuted, padded rows).
    for (int i = tid; i < Sq; i += NTHR) sm[C2_F + i] = g_c2[h * Sq + i];
    {
        const float4* xb = (const float4*)(x + (size_t)rowbase * Dq);
        #pragma unroll
        for (int it = 0; it < 8; ++it) {
            int i = it * NTHR + tid;          // 128 rows x 8 kblocks
            int r = i >> 3, kb = i & 7;
            float4 v0 = xb[r * 16 + kb * 2];
            float4 v1 = xb[r * 16 + kb * 2 + 1];
            float h0 = to_tf32(v0.x), h1 = to_tf32(v0.y),
                  h2 = to_tf32(v0.z), h3 = to_tf32(v0.w),
                  h4 = to_tf32(v1.x), h5 = to_tf32(v1.y),
                  h6 = to_tf32(v1.z), h7 = to_tf32(v1.w);
            float l0 = to_tf32(v0.x - h0), l1 = to_tf32(v0.y - h1),
                  l2 = to_tf32(v0.z - h2), l3 = to_tf32(v0.w - h3),
                  l4 = to_tf32(v1.x - h4), l5 = to_tf32(v1.y - h5),
                  l6 = to_tf32(v1.z - h6), l7 = to_tf32(v1.w - h7);
            float* dh = sm + A_F + r * RSTRIDE + kb * 8;
            // permuted order within 8-block: {k0,k4,k1,k5},{k2,k6,k3,k7}
            ((float4*)dh)[0] = make_float4(h0, h4, h1, h5);
            ((float4*)dh)[1] = make_float4(h2, h6, h3, h7);
            float* dl = dh + 64;
            ((float4*)dl)[0] = make_float4(l0, l4, l1, l5);
            ((float4*)dl)[1] = make_float4(l2, l6, l3, l7);
        }
    }
    CP_WAIT0();
    __syncthreads();

    // A fragments to registers: [tile][kblock][row-half], hi and lo.
    float2 Ah[2][8][2], Al[2][8][2];
    #pragma unroll
    for (int t = 0; t < 2; ++t)
        #pragma unroll
        for (int kb = 0; kb < 8; ++kb) {
            int r0 = wb + t * 16 + g;
            const float* b0 = sm + A_F + r0 * RSTRIDE + kb * 8 + m * 2;
            const float* b8 = b0 + 8 * RSTRIDE;
            Ah[t][kb][0] = *(const float2*)b0;
            Ah[t][kb][1] = *(const float2*)b8;
            Al[t][kb][0] = *(const float2*)(b0 + 64);
            Al[t][kb][1] = *(const float2*)(b8 + 64);
        }

    float best[4] = {3.0e38f, 3.0e38f, 3.0e38f, 3.0e38f};
    int bidx[4] = {0, 0, 0, 0};

    for (int nch = 0; nch < Sq / CH; ++nch) {        // 16 chunks of 32
        const float* Bbuf = sm + ((nch & 1) ? B1_F : B0_F);
        if (nch < Sq / CH - 1) {
            const char* src = cb_bytes + (size_t)(nch + 1) * CH * 128 * 4;
            uint32_t dstb = sb + ((nch & 1) ? B0_F : B1_F) * 4;
            #pragma unroll
            for (int j = 0; j < 8; ++j)
                cp16(dstb + cp_dst[j], src + cp_src[j]);
            CP_COMMIT();
        }

        float4 acc[4][2];                 // [colblock][tile] -> 8 indep chains
        #pragma unroll
        for (int cb = 0; cb < 4; ++cb) {
            float2 cv = *(const float2*)(sm + C2_F + nch * CH + cb * 8 + m * 2);
            #pragma unroll
            for (int t = 0; t < 2; ++t)
                acc[cb][t] = make_float4(cv.x, cv.y, cv.x, cv.y);
        }

        // kb outermost; per kb load 8 B fragments, issue 24 MMAs round-robin
        // across the 8 accumulator chains (same-chain spacing = 8).
        const float* bn0 = Bbuf + g * RSTRIDE + m * 2;
        const float* bn1 = bn0 + 8 * RSTRIDE;
        const float* bn2 = bn0 + 16 * RSTRIDE;
        const float* bn3 = bn0 + 24 * RSTRIDE;
        #pragma unroll
        for (int kb = 0; kb < 8; ++kb) {
            float2 bh0 = *(const float2*)(bn0 + kb * 8);
            float2 bh1 = *(const float2*)(bn1 + kb * 8);
            float2 bh2 = *(const float2*)(bn2 + kb * 8);
            float2 bh3 = *(const float2*)(bn3 + kb * 8);
            float2 bl0 = *(const float2*)(bn0 + 64 + kb * 8);
            float2 bl1 = *(const float2*)(bn1 + 64 + kb * 8);
            float2 bl2 = *(const float2*)(bn2 + 64 + kb * 8);
            float2 bl3 = *(const float2*)(bn3 + 64 + kb * 8);
            // term hi*hi
            mma1688(acc[0][0], Ah[0][kb][0], Ah[0][kb][1], bh0);
            mma1688(acc[0][1], Ah[1][kb][0], Ah[1][kb][1], bh0);
            mma1688(acc[1][0], Ah[0][kb][0], Ah[0][kb][1], bh1);
            mma1688(acc[1][1], Ah[1][kb][0], Ah[1][kb][1], bh1);
            mma1688(acc[2][0], Ah[0][kb][0], Ah[0][kb][1], bh2);
            mma1688(acc[2][1], Ah[1][kb][0], Ah[1][kb][1], bh2);
            mma1688(acc[3][0], Ah[0][kb][0], Ah[0][kb][1], bh3);
            mma1688(acc[3][1], Ah[1][kb][0], Ah[1][kb][1], bh3);
            // term lo*hi
            mma1688(acc[0][0], Al[0][kb][0], Al[0][kb][1], bh0);
            mma1688(acc[0][1], Al[1][kb][0], Al[1][kb][1], bh0);
            mma1688(acc[1][0], Al[0][kb][0], Al[0][kb][1], bh1);
            mma1688(acc[1][1], Al[1][kb][0], Al[1][kb][1], bh1);
            mma1688(acc[2][0], Al[0][kb][0], Al[0][kb][1], bh2);
            mma1688(acc[2][1], Al[1][kb][0], Al[1][kb][1], bh2);
            mma1688(acc[3][0], Al[0][kb][0], Al[0][kb][1], bh3);
            mma1688(acc[3][1], Al[1][kb][0], Al[1][kb][1], bh3);
            // term hi*lo
            mma1688(acc[0][0], Ah[0][kb][0], Ah[0][kb][1], bl0);
            mma1688(acc[0][1], Ah[1][kb][0], Ah[1][kb][1], bl0);
            mma1688(acc[1][0], Ah[0][kb][0], Ah[0][kb][1], bl1);
            mma1688(acc[1][1], Ah[1][kb][0], Ah[1][kb][1], bl1);
            mma1688(acc[2][0], Ah[0][kb][0], Ah[0][kb][1], bl2);
            mma1688(acc[2][1], Ah[1][kb][0], Ah[1][kb][1], bl2);
            mma1688(acc[3][0], Ah[0][kb][0], Ah[0][kb][1], bl3);
            mma1688(acc[3][1], Ah[1][kb][0], Ah[1][kb][1], bl3);
        }

        // Argmin update (ascending n, strict '<' => first-min like jnp.argmin).
        #pragma unroll
        for (int cb = 0; cb < 4; ++cb) {
            int n0 = nch * CH + cb * 8 + m * 2;
            #pragma unroll
            for (int t = 0; t < 2; ++t) {
                int s0 = t * 2, s1 = t * 2 + 1;       // rows g, g+8 (per tile)
                float4 a = acc[cb][t];
                if (a.x < best[s0]) { best[s0] = a.x; bidx[s0] = n0; }
                if (a.y < best[s0]) { best[s0] = a.y; bidx[s0] = n0 + 1; }
                if (a.z < best[s1]) { best[s1] = a.z; bidx[s1] = n0; }
                if (a.w < best[s1]) { best[s1] = a.w; bidx[s1] = n0 + 1; }
            }
        }

        CP_WAIT0();
        __syncthreads();
    }

    // Reduce across the 4 lanes (m) sharing each row; tie -> smaller index.
    #pragma unroll
    for (int s = 0; s < 4; ++s) {
        #pragma unroll
        for (int o = 1; o <= 2; o <<= 1) {
            float ob = __shfl_xor_sync(0xFFFFFFFFu, best[s], o);
            int   oi = __shfl_xor_sync(0xFFFFFFFFu, bidx[s], o);
            if (ob < best[s] || (ob == best[s] && oi < bidx[s])) {
                best[s] = ob; bidx[s] = oi;
            }
        }
    }
    if (m == 0) {
        int* si = (int*)(sm + IDX_F);
        si[wb + g]          = bidx[0];
        si[wb + g + 8]      = bidx[1];
        si[wb + 16 + g]     = bidx[2];
        si[wb + 16 + g + 8] = bidx[3];
    }
    __syncthreads();

    // Cooperative one-hot: 128 rows x 128 quads, coalesced STG.128.
    const int* si = (const int*)(sm + IDX_F);
    float4* ob4 = (float4*)(out + (size_t)rowbase * Sq);
    #pragma unroll 4
    for (int it = 0; it < 128; ++it) {
        int idx = it * NTHR + tid;
        int r = idx >> 7, c4 = idx & 127;
        int b = si[r];
        int base = c4 << 2;
        float4 v;
        v.x = (b == base)     ? 1.0f : 0.0f;
        v.y = (b == base + 1) ? 1.0f : 0.0f;
        v.z = (b == base + 2) ? 1.0f : 0.0f;
        v.w = (b == base + 3) ? 1.0f : 0.0f;
        ob4[idx] = v;
    }
}

// ---------------------------------------------------------------------------
extern "C" void kernel_launch(void* const* d_in, const int* in_sizes, int n_in,
                              void* d_out, int out_size) {
    const float* x       = (const float*)d_in[0];
    const float* c_sum   = (const float*)d_in[1];
    const float* c_count = (const float*)d_in[2];
    float* out   = (float*)d_out;
    float* out_c = out + ONEHOT_ELEMS;

    (void)in_sizes; (void)n_in; (void)out_size;

    cudaFuncSetAttribute(vq_kernel,
                         cudaFuncAttributeMaxDynamicSharedMemorySize,
                         SMEM_TOTAL);

    prep_kernel<<<Hq * Sq, 32>>>(c_sum, c_count, out_c);
    vq_kernel<<<(Bq * Hq * Lq) / ROWS, NTHR, SMEM_TOTAL>>>(x, out);
}